// round 15
// baseline (speedup 1.0000x reference)
#include <cuda_runtime.h>
#include <cuda_bf16.h>
#include <math.h>

// ConvGRU: B=8, HID=128, INP=320, C=448, H=64, W=128
#define BB   8
#define HID  128
#define INP  320
#define CC   448
#define HH   64
#define WW   128

// ---------------- device scratch (no allocation allowed) ----------------
__device__ float g_qwd[3 * CC * 9];        // fake-quant dw weights [gate][c][9]
__device__ float g_qwp[3 * CC * HID];      // fake-quant pw weights, TRANSPOSED [gate][k][m]
__device__ float g_z [BB * HID * HH * WW]; // sigmoid z gate
__device__ float g_rh[BB * HID * HH * WW]; // r * h

// ---------------- weight fake-quant kernel ----------------
// blockIdx.x: 0..5 -> (wdz, wpz, wdr, wpr, wdq, wpq)
__global__ void quant_kernel(const float* __restrict__ wdz, const float* __restrict__ wpz,
                             const float* __restrict__ wdr, const float* __restrict__ wpr,
                             const float* __restrict__ wdq, const float* __restrict__ wpq)
{
    const int t = blockIdx.x;
    const float* src; int n; float* dst; bool trans;
    switch (t) {
        case 0: src = wdz; n = CC * 9;   dst = g_qwd;                trans = false; break;
        case 1: src = wpz; n = CC * HID; dst = g_qwp;                trans = true;  break;
        case 2: src = wdr; n = CC * 9;   dst = g_qwd + CC * 9;       trans = false; break;
        case 3: src = wpr; n = CC * HID; dst = g_qwp + CC * HID;     trans = true;  break;
        case 4: src = wdq; n = CC * 9;   dst = g_qwd + 2 * CC * 9;   trans = false; break;
        default:src = wpq; n = CC * HID; dst = g_qwp + 2 * CC * HID; trans = true;  break;
    }
    const int tid = threadIdx.x;

    // per-tensor max(|w|)
    float m = 0.f;
    for (int i = tid; i < n; i += 256) m = fmaxf(m, fabsf(src[i]));
    __shared__ float red[8];
    #pragma unroll
    for (int o = 16; o > 0; o >>= 1) m = fmaxf(m, __shfl_xor_sync(0xffffffffu, m, o));
    if ((tid & 31) == 0) red[tid >> 5] = m;
    __syncthreads();
    if (tid < 8) {
        float v = red[tid];
        #pragma unroll
        for (int o = 4; o > 0; o >>= 1) v = fmaxf(v, __shfl_xor_sync(0xffu, v, o));
        if (tid == 0) red[0] = v;
    }
    __syncthreads();
    const float scale = fmaxf(red[0], 1e-8f) / 127.f;

    for (int i = tid; i < n; i += 256) {
        float q = rintf(src[i] / scale);          // round-half-even, matches jnp.round
        q = fminf(fmaxf(q, -128.f), 127.f) * scale;
        if (trans) {
            int mo = i / CC, k = i - mo * CC;     // src [M=128][K=448] -> dst [K][M]
            dst[k * HID + mo] = q;
        } else {
            dst[i] = q;
        }
    }
}

// ---------------- fused dwconv3x3 + pwconv1x1 + epilogue ----------------
// One block = one (b, y) row: 128 pixels x 128 output channels.
// K loop over 448 channels in chunks of 32; 256 threads; 8x8 regs/thread.
//
// smem layout (floats):
//   s_in : 32ch * 3rows * 130cols = 12480   (cols 0 and 129 are zero padding)
//   s_dw : 32 * 128                = 4096
//   s_wp : 32 * 128                = 4096   ([k][m])
//   s_wd : 32 * 9                  = 288
#define S_IN  0
#define S_DW  12480
#define S_WP  16576
#define S_WD  20672
#define SMEM_FLOATS 20960
#define SMEM_BYTES  (SMEM_FLOATS * 4)

// mode: 0 = z (store sigmoid), 1 = r (store sigmoid*h), 2 = q (store final out)
__global__ __launch_bounds__(256, 2)
void gate_kernel(const float* __restrict__ low,   // channels 0..127  (h, or rh for q)
                 const float* __restrict__ xin,   // channels 128..447 (x)
                 const float* __restrict__ qwd,   // [448][9]
                 const float* __restrict__ bd,    // [448]
                 const float* __restrict__ qwp,   // [448][128] k-major
                 const float* __restrict__ bp,    // [128]
                 const float* __restrict__ hbuf,  // h (modes 1,2)
                 const float* __restrict__ zbuf,  // z (mode 2)
                 float* __restrict__ out,
                 int mode)
{
    extern __shared__ float sm[];
    float* s_in = sm + S_IN;
    float* s_dw = sm + S_DW;
    float* s_wp = sm + S_WP;
    float* s_wd = sm + S_WD;

    const int tid  = threadIdx.x;
    const int bi   = blockIdx.x >> 6;   // batch
    const int y    = blockIdx.x & 63;   // image row
    const int wid  = tid >> 5;
    const int lane = tid & 31;

    float acc[8][8];
    #pragma unroll
    for (int i = 0; i < 8; ++i)
        #pragma unroll
        for (int j = 0; j < 8; ++j) acc[i][j] = 0.f;

    const int mrow = (tid >> 4) << 3;
    const int pcol = (tid & 15) << 3;

    for (int c0 = 0; c0 < CC; c0 += 32) {
        __syncthreads();  // previous GEMM done reading s_dw/s_wp/s_in

        // ---- stage weights ----
        // NOTE: 288 > blockDim (256) -> must stride!  (Round 14 bug: `if (tid<288)`
        // left s_wd[256..287] as garbage -> rel_err 0.275)
        for (int i = tid; i < 288; i += 256) s_wd[i] = qwd[c0 * 9 + i];
        #pragma unroll
        for (int i = tid; i < 4096; i += 256) s_wp[i] = qwp[c0 * HID + i];

        // ---- stage input tile (32ch x 3rows x 130cols, zero-padded) ----
        for (int r = wid; r < 96; r += 8) {
            const int cl = r / 3;
            const int ry = r - cl * 3;
            const int c  = c0 + cl;
            const int ys = y + ry - 1;
            float* dst = &s_in[r * 130];
            if ((unsigned)ys < (unsigned)HH) {
                const float* srcp = (c < HID)
                    ? (low + (((size_t)bi * HID + c) * HH + ys) * WW)
                    : (xin + (((size_t)bi * INP + (c - HID)) * HH + ys) * WW);
                for (int col = lane; col < 130; col += 32)
                    dst[col] = (col >= 1 && col <= 128) ? srcp[col - 1] : 0.f;
            } else {
                for (int col = lane; col < 130; col += 32) dst[col] = 0.f;
            }
        }
        __syncthreads();

        // ---- depthwise 3x3 into s_dw (with dw bias) ----
        #pragma unroll 4
        for (int t = 0; t < 16; ++t) {
            const int j = t * 256 + tid;
            const int k = j >> 7;
            const int p = j & 127;
            const float* wk = &s_wd[k * 9];
            const float* r0 = &s_in[(k * 3 + 0) * 130 + p];
            const float* r1 = r0 + 130;
            const float* r2 = r1 + 130;
            float s = bd[c0 + k];
            s += r0[0] * wk[0] + r0[1] * wk[1] + r0[2] * wk[2];
            s += r1[0] * wk[3] + r1[1] * wk[4] + r1[2] * wk[5];
            s += r2[0] * wk[6] + r2[1] * wk[7] + r2[2] * wk[8];
            s_dw[k * 128 + p] = s;
        }
        __syncthreads();

        // ---- GEMM micro-kernel: acc[m][p] += wp[k][m] * dw[k][p] ----
        #pragma unroll 4
        for (int kk = 0; kk < 32; ++kk) {
            float4 a0 = *(const float4*)&s_wp[kk * 128 + mrow];
            float4 a1 = *(const float4*)&s_wp[kk * 128 + mrow + 4];
            float4 b0 = *(const float4*)&s_dw[kk * 128 + pcol];
            float4 b1 = *(const float4*)&s_dw[kk * 128 + pcol + 4];
            float av[8] = {a0.x, a0.y, a0.z, a0.w, a1.x, a1.y, a1.z, a1.w};
            float bv[8] = {b0.x, b0.y, b0.z, b0.w, b1.x, b1.y, b1.z, b1.w};
            #pragma unroll
            for (int i = 0; i < 8; ++i)
                #pragma unroll
                for (int j = 0; j < 8; ++j)
                    acc[i][j] += av[i] * bv[j];
        }
    }

    // ---- epilogue ----
    #pragma unroll
    for (int i = 0; i < 8; ++i) {
        const int m = mrow + i;
        const float bias = bp[m];
        const size_t base = (((size_t)bi * HID + m) * HH + y) * WW + pcol;
        if (mode == 0) {
            #pragma unroll
            for (int j = 0; j < 8; ++j) {
                float v = acc[i][j] + bias;
                out[base + j] = 1.f / (1.f + expf(-v));
            }
        } else if (mode == 1) {
            #pragma unroll
            for (int j = 0; j < 8; ++j) {
                float v = 1.f / (1.f + expf(-(acc[i][j] + bias)));
                out[base + j] = v * hbuf[base + j];
            }
        } else {
            #pragma unroll
            for (int j = 0; j < 8; ++j) {
                float q  = tanhf(acc[i][j] + bias);
                float zv = zbuf[base + j];
                float hv = hbuf[base + j];
                out[base + j] = (1.f - zv) * hv + zv * q;
            }
        }
    }
}

// ---------------- launch ----------------
extern "C" void kernel_launch(void* const* d_in, const int* in_sizes, int n_in,
                              void* d_out, int out_size)
{
    const float* h   = (const float*)d_in[0];
    const float* x   = (const float*)d_in[1];
    const float* wdz = (const float*)d_in[2];
    const float* bdz = (const float*)d_in[3];
    const float* wpz = (const float*)d_in[4];
    const float* bpz = (const float*)d_in[5];
    const float* wdr = (const float*)d_in[6];
    const float* bdr = (const float*)d_in[7];
    const float* wpr = (const float*)d_in[8];
    const float* bpr = (const float*)d_in[9];
    const float* wdq = (const float*)d_in[10];
    const float* bdq = (const float*)d_in[11];
    const float* wpq = (const float*)d_in[12];
    const float* bpq = (const float*)d_in[13];
    float* out = (float*)d_out;

    cudaFuncSetAttribute(gate_kernel, cudaFuncAttributeMaxDynamicSharedMemorySize, SMEM_BYTES);

    float* qwd; cudaGetSymbolAddress((void**)&qwd, g_qwd);
    float* qwp; cudaGetSymbolAddress((void**)&qwp, g_qwp);
    float* zb;  cudaGetSymbolAddress((void**)&zb,  g_z);
    float* rhb; cudaGetSymbolAddress((void**)&rhb, g_rh);

    quant_kernel<<<6, 256>>>(wdz, wpz, wdr, wpr, wdq, wpq);

    const int grid = BB * HH;  // 512 blocks: one per (batch, row)

    // z gate
    gate_kernel<<<grid, 256, SMEM_BYTES>>>(h, x, qwd,            bdz, qwp,            bpz,
                                           h, nullptr, zb, 0);
    // r gate -> rh = sigmoid(.) * h
    gate_kernel<<<grid, 256, SMEM_BYTES>>>(h, x, qwd + CC*9,     bdr, qwp + CC*HID,   bpr,
                                           h, nullptr, rhb, 1);
    // q gate -> out = (1-z)h + z*tanh(.)
    gate_kernel<<<grid, 256, SMEM_BYTES>>>(rhb, x, qwd + 2*CC*9, bdq, qwp + 2*CC*HID, bpq,
                                           h, zb, out, 2);
}

// round 16
// speedup vs baseline: 1.0019x; 1.0019x over previous
#include <cuda_runtime.h>
#include <cuda_bf16.h>
#include <math.h>

// ConvGRU: B=8, HID=128, INP=320, C=448, H=64, W=128
#define BB   8
#define HID  128
#define INP  320
#define CC   448
#define HH   64
#define WW   128

// ---------------- device scratch (no allocation allowed) ----------------
__device__ float g_qwd[3 * CC * 9];        // fake-quant dw weights [gate][c][9]
__device__ float g_qwp[3 * CC * HID];      // fake-quant pw weights, TRANSPOSED [gate][k][m]
__device__ float g_z [BB * HID * HH * WW]; // sigmoid z gate
__device__ float g_rh[BB * HID * HH * WW]; // r * h

// ---------------- weight fake-quant kernel ----------------
// blockIdx.x: 0..5 -> (wdz, wpz, wdr, wpr, wdq, wpq)
__global__ void quant_kernel(const float* __restrict__ wdz, const float* __restrict__ wpz,
                             const float* __restrict__ wdr, const float* __restrict__ wpr,
                             const float* __restrict__ wdq, const float* __restrict__ wpq)
{
    const int t = blockIdx.x;
    const float* src; int n; float* dst; bool trans;
    switch (t) {
        case 0: src = wdz; n = CC * 9;   dst = g_qwd;                trans = false; break;
        case 1: src = wpz; n = CC * HID; dst = g_qwp;                trans = true;  break;
        case 2: src = wdr; n = CC * 9;   dst = g_qwd + CC * 9;       trans = false; break;
        case 3: src = wpr; n = CC * HID; dst = g_qwp + CC * HID;     trans = true;  break;
        case 4: src = wdq; n = CC * 9;   dst = g_qwd + 2 * CC * 9;   trans = false; break;
        default:src = wpq; n = CC * HID; dst = g_qwp + 2 * CC * HID; trans = true;  break;
    }
    const int tid = threadIdx.x;

    // per-tensor max(|w|)
    float m = 0.f;
    for (int i = tid; i < n; i += 256) m = fmaxf(m, fabsf(src[i]));
    __shared__ float red[8];
    #pragma unroll
    for (int o = 16; o > 0; o >>= 1) m = fmaxf(m, __shfl_xor_sync(0xffffffffu, m, o));
    if ((tid & 31) == 0) red[tid >> 5] = m;
    __syncthreads();
    if (tid < 8) {
        float v = red[tid];
        #pragma unroll
        for (int o = 4; o > 0; o >>= 1) v = fmaxf(v, __shfl_xor_sync(0xffu, v, o));
        if (tid == 0) red[0] = v;
    }
    __syncthreads();
    const float scale = fmaxf(red[0], 1e-8f) / 127.f;

    for (int i = tid; i < n; i += 256) {
        float q = rintf(src[i] / scale);          // round-half-even, matches jnp.round
        q = fminf(fmaxf(q, -128.f), 127.f) * scale;
        if (trans) {
            int mo = i / CC, k = i - mo * CC;     // src [M=128][K=448] -> dst [K][M]
            dst[k * HID + mo] = q;
        } else {
            dst[i] = q;
        }
    }
}

// ---------------- fused dwconv3x3 + pwconv1x1 + epilogue ----------------
// One block = one (b, y) row: 128 pixels x 128 output channels.
// K loop over 448 channels in chunks of 32; 256 threads; 8x8 regs/thread.
//
// smem layout (floats):
//   s_in : 32ch * 3rows * 130cols = 12480   (cols 0 and 129 are zero padding)
//   s_dw : 32 * 128                = 4096
//   s_wp : 32 * 128                = 4096   ([k][m])
//   s_wd : 32 * 9                  = 288
#define S_IN  0
#define S_DW  12480
#define S_WP  16576
#define S_WD  20672
#define SMEM_FLOATS 20960
#define SMEM_BYTES  (SMEM_FLOATS * 4)

// mode: 0 = z (store sigmoid), 1 = r (store sigmoid*h), 2 = q (store final out)
__global__ __launch_bounds__(256, 2)
void gate_kernel(const float* __restrict__ low,   // channels 0..127  (h, or rh for q)
                 const float* __restrict__ xin,   // channels 128..447 (x)
                 const float* __restrict__ qwd,   // [448][9]
                 const float* __restrict__ bd,    // [448]
                 const float* __restrict__ qwp,   // [448][128] k-major
                 const float* __restrict__ bp,    // [128]
                 const float* __restrict__ hbuf,  // h (modes 1,2)
                 const float* __restrict__ zbuf,  // z (mode 2)
                 float* __restrict__ out,
                 int mode)
{
    extern __shared__ float sm[];
    float* s_in = sm + S_IN;
    float* s_dw = sm + S_DW;
    float* s_wp = sm + S_WP;
    float* s_wd = sm + S_WD;

    const int tid  = threadIdx.x;
    const int bi   = blockIdx.x >> 6;   // batch
    const int y    = blockIdx.x & 63;   // image row
    const int wid  = tid >> 5;
    const int lane = tid & 31;

    float acc[8][8];
    #pragma unroll
    for (int i = 0; i < 8; ++i)
        #pragma unroll
        for (int j = 0; j < 8; ++j) acc[i][j] = 0.f;

    const int mrow = (tid >> 4) << 3;
    const int pcol = (tid & 15) << 3;

    for (int c0 = 0; c0 < CC; c0 += 32) {
        __syncthreads();  // previous GEMM done reading s_dw/s_wp/s_in

        // ---- stage weights ----
        // NOTE: 288 > blockDim (256) -> must stride!  (Round 14 bug: `if (tid<288)`
        // left s_wd[256..287] as garbage -> rel_err 0.275)
        for (int i = tid; i < 288; i += 256) s_wd[i] = qwd[c0 * 9 + i];
        #pragma unroll
        for (int i = tid; i < 4096; i += 256) s_wp[i] = qwp[c0 * HID + i];

        // ---- stage input tile (32ch x 3rows x 130cols, zero-padded) ----
        for (int r = wid; r < 96; r += 8) {
            const int cl = r / 3;
            const int ry = r - cl * 3;
            const int c  = c0 + cl;
            const int ys = y + ry - 1;
            float* dst = &s_in[r * 130];
            if ((unsigned)ys < (unsigned)HH) {
                const float* srcp = (c < HID)
                    ? (low + (((size_t)bi * HID + c) * HH + ys) * WW)
                    : (xin + (((size_t)bi * INP + (c - HID)) * HH + ys) * WW);
                for (int col = lane; col < 130; col += 32)
                    dst[col] = (col >= 1 && col <= 128) ? srcp[col - 1] : 0.f;
            } else {
                for (int col = lane; col < 130; col += 32) dst[col] = 0.f;
            }
        }
        __syncthreads();

        // ---- depthwise 3x3 into s_dw (with dw bias) ----
        #pragma unroll 4
        for (int t = 0; t < 16; ++t) {
            const int j = t * 256 + tid;
            const int k = j >> 7;
            const int p = j & 127;
            const float* wk = &s_wd[k * 9];
            const float* r0 = &s_in[(k * 3 + 0) * 130 + p];
            const float* r1 = r0 + 130;
            const float* r2 = r1 + 130;
            float s = bd[c0 + k];
            s += r0[0] * wk[0] + r0[1] * wk[1] + r0[2] * wk[2];
            s += r1[0] * wk[3] + r1[1] * wk[4] + r1[2] * wk[5];
            s += r2[0] * wk[6] + r2[1] * wk[7] + r2[2] * wk[8];
            s_dw[k * 128 + p] = s;
        }
        __syncthreads();

        // ---- GEMM micro-kernel: acc[m][p] += wp[k][m] * dw[k][p] ----
        #pragma unroll 4
        for (int kk = 0; kk < 32; ++kk) {
            float4 a0 = *(const float4*)&s_wp[kk * 128 + mrow];
            float4 a1 = *(const float4*)&s_wp[kk * 128 + mrow + 4];
            float4 b0 = *(const float4*)&s_dw[kk * 128 + pcol];
            float4 b1 = *(const float4*)&s_dw[kk * 128 + pcol + 4];
            float av[8] = {a0.x, a0.y, a0.z, a0.w, a1.x, a1.y, a1.z, a1.w};
            float bv[8] = {b0.x, b0.y, b0.z, b0.w, b1.x, b1.y, b1.z, b1.w};
            #pragma unroll
            for (int i = 0; i < 8; ++i)
                #pragma unroll
                for (int j = 0; j < 8; ++j)
                    acc[i][j] += av[i] * bv[j];
        }
    }

    // ---- epilogue ----
    #pragma unroll
    for (int i = 0; i < 8; ++i) {
        const int m = mrow + i;
        const float bias = bp[m];
        const size_t base = (((size_t)bi * HID + m) * HH + y) * WW + pcol;
        if (mode == 0) {
            #pragma unroll
            for (int j = 0; j < 8; ++j) {
                float v = acc[i][j] + bias;
                out[base + j] = 1.f / (1.f + expf(-v));
            }
        } else if (mode == 1) {
            #pragma unroll
            for (int j = 0; j < 8; ++j) {
                float v = 1.f / (1.f + expf(-(acc[i][j] + bias)));
                out[base + j] = v * hbuf[base + j];
            }
        } else {
            #pragma unroll
            for (int j = 0; j < 8; ++j) {
                float q  = tanhf(acc[i][j] + bias);
                float zv = zbuf[base + j];
                float hv = hbuf[base + j];
                out[base + j] = (1.f - zv) * hv + zv * q;
            }
        }
    }
}

// ---------------- launch ----------------
extern "C" void kernel_launch(void* const* d_in, const int* in_sizes, int n_in,
                              void* d_out, int out_size)
{
    const float* h   = (const float*)d_in[0];
    const float* x   = (const float*)d_in[1];
    const float* wdz = (const float*)d_in[2];
    const float* bdz = (const float*)d_in[3];
    const float* wpz = (const float*)d_in[4];
    const float* bpz = (const float*)d_in[5];
    const float* wdr = (const float*)d_in[6];
    const float* bdr = (const float*)d_in[7];
    const float* wpr = (const float*)d_in[8];
    const float* bpr = (const float*)d_in[9];
    const float* wdq = (const float*)d_in[10];
    const float* bdq = (const float*)d_in[11];
    const float* wpq = (const float*)d_in[12];
    const float* bpq = (const float*)d_in[13];
    float* out = (float*)d_out;

    cudaFuncSetAttribute(gate_kernel, cudaFuncAttributeMaxDynamicSharedMemorySize, SMEM_BYTES);

    float* qwd; cudaGetSymbolAddress((void**)&qwd, g_qwd);
    float* qwp; cudaGetSymbolAddress((void**)&qwp, g_qwp);
    float* zb;  cudaGetSymbolAddress((void**)&zb,  g_z);
    float* rhb; cudaGetSymbolAddress((void**)&rhb, g_rh);

    quant_kernel<<<6, 256>>>(wdz, wpz, wdr, wpr, wdq, wpq);

    const int grid = BB * HH;  // 512 blocks: one per (batch, row)

    // z gate
    gate_kernel<<<grid, 256, SMEM_BYTES>>>(h, x, qwd,            bdz, qwp,            bpz,
                                           h, nullptr, zb, 0);
    // r gate -> rh = sigmoid(.) * h
    gate_kernel<<<grid, 256, SMEM_BYTES>>>(h, x, qwd + CC*9,     bdr, qwp + CC*HID,   bpr,
                                           h, nullptr, rhb, 1);
    // q gate -> out = (1-z)h + z*tanh(.)
    gate_kernel<<<grid, 256, SMEM_BYTES>>>(rhb, x, qwd + 2*CC*9, bdq, qwp + 2*CC*HID, bpq,
                                           h, zb, out, 2);
}